// round 2
// baseline (speedup 1.0000x reference)
#include <cuda_runtime.h>
#include <math.h>

#define D1 768
#define D2 768
#define D2R 385
#define NF (D1*D2R)     // 295680
#define KN_ 4
#define B_ 8
#define C_ 256
#define HW_ 64

// ---------------- scratch (static device globals; no allocation) ----------
__device__ float  g_att[B_*KN_];
__device__ float2 g_tw[D1];                 // (cos, sin) of 2*pi*j/768
__device__ float  g_Gr[KN_][NF];            // scattered freq map, real  [p][q]
__device__ float  g_Gi[KN_][NF];            //                      imag
__device__ float  g_Yr[KN_][NF];            // after axis-0 ifft (scaled) [m][q]
__device__ float  g_Yi[KN_][NF];
__device__ float  g_S [KN_][D1*D2];         // spatial weights [m][t]
__device__ float  g_Wb[B_][C_*C_*9];        // per-batch conv W, K-major: [(i*9+st)*256 + o]

// ---------------- setup: attention + twiddle table -------------------------
__global__ void k_setup(const float* __restrict__ katt) {
    int j = threadIdx.x;
    if (j < D1) {
        double ang = 2.0 * M_PI * (double)j / (double)D1;
        g_tw[j] = make_float2((float)cos(ang), (float)sin(ang));
    }
    if (j < B_*KN_) {
        // sigmoid(a/1.0) * 2/4
        g_att[j] = 0.5f / (1.0f + expf(-katt[j]));
    }
}

// ---------------- scatter dft_weight into dense rfft2 grid -----------------
__global__ void k_scatter(const float* __restrict__ dw,
                          const int*   __restrict__ fh,
                          const int*   __restrict__ fw) {
    int n = blockIdx.x * 256 + threadIdx.x;
    if (n >= NF) return;
    int pos = fh[n] * D2R + fw[n];
    const float2* dw2 = (const float2*)dw;
#pragma unroll
    for (int k = 0; k < KN_; ++k) {
        float2 v = dw2[k*NF + n];
        g_Gr[k][pos] = v.x;
        g_Gi[k][pos] = v.y;
    }
}

// ---------------- axis-0 complex inverse DFT (length 768) ------------------
// Y[m][q] = scale(q) * sum_p G[p][q] * exp(+2*pi*i*m*p/768)
// scale folds 1/(768*768) and rfft fold weight wq (and zeroes imag at q=0,384)
__global__ void __launch_bounds__(256) k_dftP() {
    __shared__ float2 stw[D1];
    __shared__ float  sGr[32][33];
    __shared__ float  sGi[32][33];
    int k  = blockIdx.z;
    int q0 = blockIdx.x * 32;
    int m0 = blockIdx.y * 64;
    int tx = threadIdx.x, ty = threadIdx.y;
    int tid = ty*32 + tx;
    for (int j = tid; j < D1; j += 256) stw[j] = g_tw[j];

    int q = q0 + tx;
    bool qv = (q < D2R);

    float accr[8], acci[8];
    int   jm[8], ms[8];
#pragma unroll
    for (int mm = 0; mm < 8; ++mm) {
        accr[mm] = 0.f; acci[mm] = 0.f;
        ms[mm] = m0 + ty*8 + mm;
        jm[mm] = 0;                       // (m*0) % 768
    }

    for (int p0 = 0; p0 < D1; p0 += 32) {
        __syncthreads();
#pragma unroll
        for (int r = 0; r < 4; ++r) {
            int pl = ty*4 + r;            // 0..31
            int p  = p0 + pl;
            sGr[pl][tx] = qv ? g_Gr[k][p*D2R + q] : 0.f;
            sGi[pl][tx] = qv ? g_Gi[k][p*D2R + q] : 0.f;
        }
        __syncthreads();
#pragma unroll
        for (int pl = 0; pl < 32; ++pl) {
            float gr = sGr[pl][tx];
            float gi = sGi[pl][tx];
#pragma unroll
            for (int mm = 0; mm < 8; ++mm) {
                float2 cs = stw[jm[mm]];          // warp-uniform -> broadcast
                accr[mm] += cs.x*gr - cs.y*gi;
                acci[mm] += cs.x*gi + cs.y*gr;
                jm[mm] += ms[mm];
                if (jm[mm] >= D1) jm[mm] -= D1;
            }
        }
    }

    if (qv) {
        bool edge = (q == 0) || (q == 384);
        float sc  = (edge ? 1.f : 2.f) * (1.f/((float)D1*(float)D2));
        float sci = edge ? 0.f : sc;      // imag of DC/Nyquist is ignored by irfft
#pragma unroll
        for (int mm = 0; mm < 8; ++mm) {
            g_Yr[k][ms[mm]*D2R + q] = accr[mm]*sc;
            g_Yi[k][ms[mm]*D2R + q] = acci[mm]*sci;
        }
    }
}

// ---------------- axis-1 irfft (385 -> 768 real) ---------------------------
// S[m][t] = sum_q ( Yr[m][q]*cos(2*pi*q*t/768) - Yi[m][q]*sin(...) )
__global__ void __launch_bounds__(256) k_irfftQ() {
    __shared__ float2 stw[D1];
    __shared__ __align__(16) float sYr[32][68];
    __shared__ __align__(16) float sYi[32][68];
    int k  = blockIdx.z;
    int t0 = blockIdx.x * 32;
    int m0 = blockIdx.y * 64;
    int tx = threadIdx.x, ty = threadIdx.y;
    int tid = ty*32 + tx;
    for (int j = tid; j < D1; j += 256) stw[j] = g_tw[j];

    int t = t0 + tx;
    float acc[8];
#pragma unroll
    for (int mm = 0; mm < 8; ++mm) acc[mm] = 0.f;
    int jq = 0;                           // (q*t) % 768, q starts at 0

    for (int q0 = 0; q0 < D2R; q0 += 32) {
        __syncthreads();
#pragma unroll
        for (int r = 0; r < 8; ++r) {
            int ml = ty*8 + r;            // 0..63
            int q  = q0 + tx;
            bool v = (q < D2R);
            sYr[tx][ml] = v ? g_Yr[k][(m0+ml)*D2R + q] : 0.f;
            sYi[tx][ml] = v ? g_Yi[k][(m0+ml)*D2R + q] : 0.f;
        }
        __syncthreads();
#pragma unroll
        for (int ql = 0; ql < 32; ++ql) {
            float2 cs = stw[jq];
            const float4* pr = (const float4*)&sYr[ql][ty*8];
            const float4* pi = (const float4*)&sYi[ql][ty*8];
            float4 r0 = pr[0], r1 = pr[1];
            float4 i0 = pi[0], i1 = pi[1];
            acc[0] += cs.x*r0.x - cs.y*i0.x;
            acc[1] += cs.x*r0.y - cs.y*i0.y;
            acc[2] += cs.x*r0.z - cs.y*i0.z;
            acc[3] += cs.x*r0.w - cs.y*i0.w;
            acc[4] += cs.x*r1.x - cs.y*i1.x;
            acc[5] += cs.x*r1.y - cs.y*i1.y;
            acc[6] += cs.x*r1.z - cs.y*i1.z;
            acc[7] += cs.x*r1.w - cs.y*i1.w;
            jq += t;
            if (jq >= D1) jq -= D1;
        }
    }
#pragma unroll
    for (int mm = 0; mm < 8; ++mm)
        g_S[k][(m0 + ty*8 + mm)*D2 + t] = acc[mm];
}

// ---------------- combine per-batch weights (K-major for conv) -------------
// g_Wb[b][(i*9+st)*256 + o] = sum_k att[b][k] * S_k[o*3+s][i*3+t]
__global__ void k_combine() {
    int id = blockIdx.x * 256 + threadIdx.x;   // 0 .. 8*256*9*256-1
    int o  = id & 255;
    int r  = id >> 8;        // = b*2304 + i*9 + st
    int st = r % 9;
    int r2 = r / 9;
    int i  = r2 & 255;
    int b  = r2 >> 8;
    int s  = st / 3, tt = st % 3;
    int sidx = (o*3 + s)*D2 + i*3 + tt;
    float v = 0.f;
#pragma unroll
    for (int k = 0; k < KN_; ++k)
        v += g_att[b*KN_ + k] * g_S[k][sidx];
    g_Wb[b][(i*9 + st)*256 + o] = v;
}

// ---------------- grouped 3x3 conv, per batch ------------------------------
// block: 64 out-channels x (4x16) pixel tile; thread: 4 o x 4 pix
__global__ void __launch_bounds__(256) k_conv(const float* __restrict__ xin,
                                              float* __restrict__ out) {
    __shared__ __align__(16) float sX[8][6][20];   // 8 in-ch x (4+2) x (16+2), padded
    __shared__ __align__(16) float sW[8][9][64];   // [i][st][o]
    int b    = blockIdx.z;
    int o0   = blockIdx.y * 64;
    int tile = blockIdx.x;               // 0..63
    int y0 = (tile >> 2) * 4;
    int x0 = (tile & 3) * 16;
    int tid = threadIdx.x;
    int to = tid >> 4;                   // 0..15 -> 4 o's each
    int tp = tid & 15;                   // 0..15 -> 4 pix each
    int py = tp >> 2;                    // 0..3
    int px = (tp & 3) * 4;               // 0,4,8,12

    const float* xb = xin + (size_t)b * C_ * HW_ * HW_;
    const float* wb = g_Wb[b];

    float acc[4][4];
#pragma unroll
    for (int a = 0; a < 4; ++a)
#pragma unroll
        for (int j = 0; j < 4; ++j) acc[a][j] = 0.f;

    for (int i0 = 0; i0 < C_; i0 += 8) {
        __syncthreads();
        // load x patch: 8 x 6 x 18 = 864 elements
        for (int idx = tid; idx < 8*6*18; idx += 256) {
            int il = idx / 108;
            int r  = idx % 108;
            int ry = r / 18, rx = r % 18;
            int iy = y0 + ry - 1, ix = x0 + rx - 1;
            float v = 0.f;
            if (iy >= 0 && iy < HW_ && ix >= 0 && ix < HW_)
                v = xb[(i0 + il)*(HW_*HW_) + iy*HW_ + ix];
            sX[il][ry][rx] = v;
        }
        // load weights: 8*9*64 = 4608 elements, coalesced (K-major layout)
        float* sWf = &sW[0][0][0];
        for (int idx = tid; idx < 8*9*64; idx += 256) {
            int ol = idx & 63;
            int r  = idx >> 6;           // i*9 + st
            sWf[idx] = wb[((i0 + r/9)*9 + (r%9))*256 + o0 + ol];
        }
        __syncthreads();
#pragma unroll
        for (int il = 0; il < 8; ++il) {
            float xr[3][6];
#pragma unroll
            for (int dy = 0; dy < 3; ++dy)
#pragma unroll
                for (int j = 0; j < 6; ++j)
                    xr[dy][j] = sX[il][py + dy][px + j];
#pragma unroll
            for (int dy = 0; dy < 3; ++dy)
#pragma unroll
                for (int dx = 0; dx < 3; ++dx) {
                    float4 w4 = *(const float4*)&sW[il][dy*3 + dx][to*4];
#pragma unroll
                    for (int j = 0; j < 4; ++j) {
                        float xv = xr[dy][j + dx];
                        acc[0][j] += w4.x * xv;
                        acc[1][j] += w4.y * xv;
                        acc[2][j] += w4.z * xv;
                        acc[3][j] += w4.w * xv;
                    }
                }
        }
    }

    float* ob = out + (size_t)b * C_ * HW_ * HW_;
#pragma unroll
    for (int oo = 0; oo < 4; ++oo) {
        int o = o0 + to*4 + oo;
        float4 v = make_float4(acc[oo][0], acc[oo][1], acc[oo][2], acc[oo][3]);
        *(float4*)&ob[o*(HW_*HW_) + (y0 + py)*HW_ + x0 + px] = v;
    }
}

// ---------------- launch ----------------------------------------------------
extern "C" void kernel_launch(void* const* d_in, const int* in_sizes, int n_in,
                              void* d_out, int out_size) {
    const float* x    = (const float*)d_in[0];
    const float* dw   = (const float*)d_in[1];
    const float* katt = (const float*)d_in[2];
    const int*   fh   = (const int*)d_in[3];
    const int*   fw   = (const int*)d_in[4];
    float* out = (float*)d_out;

    k_setup  <<<1, 768>>>(katt);
    k_scatter<<<(NF + 255)/256, 256>>>(dw, fh, fw);
    k_dftP   <<<dim3(13, 12, KN_), dim3(32, 8)>>>();
    k_irfftQ <<<dim3(24, 12, KN_), dim3(32, 8)>>>();
    k_combine<<<(B_*C_*C_*9)/256, 256>>>();
    k_conv   <<<dim3(64, 4, B_), 256>>>(x, out);
}

// round 4
// speedup vs baseline: 1.3663x; 1.3663x over previous
#include <cuda_runtime.h>
#include <cuda_bf16.h>
#include <mma.h>
#include <math.h>
#include <stdint.h>

using namespace nvcuda;

#define D1 768
#define D2 768
#define D2R 385
#define NF (D1*D2R)     // 295680
#define KN_ 4
#define B_ 8
#define C_ 256
#define HW_ 64

// ---------------- scratch (static device globals; no allocation) ----------
__device__ float  g_att[B_*KN_];
__device__ float2 g_tw[D1];                 // (cos, sin) of 2*pi*j/768
__device__ float  g_Gr[KN_][NF];            // scattered freq map, real  [p][q]
__device__ float  g_Gi[KN_][NF];            //                      imag
__device__ float  g_Yr[KN_][NF];            // after axis-0 ifft (scaled) [m][q]
__device__ float  g_Yi[KN_][NF];
__device__ float  g_S [KN_][D1*D2];         // spatial weights [m][t]

// bf16 hi/lo weights, per batch, K-major rows: [b][o][st*256 + i]
__device__ __align__(128) __nv_bfloat16 g_Whi[B_*C_*9*C_];
__device__ __align__(128) __nv_bfloat16 g_Wlo[B_*C_*9*C_];
// bf16 hi/lo input, channel-last: [b][pixel][i]
__device__ __align__(128) __nv_bfloat16 g_Xhi[B_*HW_*HW_*C_];
__device__ __align__(128) __nv_bfloat16 g_Xlo[B_*HW_*HW_*C_];

// ============================ helpers ======================================
__device__ __forceinline__ uint32_t smem_u32(const void* p) {
    uint32_t a;
    asm("{ .reg .u64 t; cvta.to.shared.u64 t, %1; cvt.u32.u64 %0, t; }"
        : "=r"(a) : "l"(p));
    return a;
}
__device__ __forceinline__ void cp_async16(uint32_t dst, const void* src, int pbytes) {
    asm volatile("cp.async.cg.shared.global [%0], [%1], 16, %2;"
                 :: "r"(dst), "l"(src), "r"(pbytes));
}
#define CP_COMMIT() asm volatile("cp.async.commit_group;" ::: "memory")
#define CP_WAIT(N)  asm volatile("cp.async.wait_group %0;" :: "n"(N) : "memory")

// ---------------- setup: attention + twiddle table -------------------------
__global__ void k_setup(const float* __restrict__ katt) {
    int j = threadIdx.x;
    if (j < D1) {
        double ang = 2.0 * M_PI * (double)j / (double)D1;
        g_tw[j] = make_float2((float)cos(ang), (float)sin(ang));
    }
    if (j < B_*KN_) {
        g_att[j] = 0.5f / (1.0f + expf(-katt[j]));
    }
}

// ---------------- scatter dft_weight into dense rfft2 grid -----------------
__global__ void k_scatter(const float* __restrict__ dw,
                          const int*   __restrict__ fh,
                          const int*   __restrict__ fw) {
    int n = blockIdx.x * 256 + threadIdx.x;
    if (n >= NF) return;
    int pos = fh[n] * D2R + fw[n];
    const float2* dw2 = (const float2*)dw;
#pragma unroll
    for (int k = 0; k < KN_; ++k) {
        float2 v = dw2[k*NF + n];
        g_Gr[k][pos] = v.x;
        g_Gi[k][pos] = v.y;
    }
}

// ---------------- axis-0 complex inverse DFT (length 768) ------------------
__global__ void __launch_bounds__(256) k_dftP() {
    __shared__ float2 stw[D1];
    __shared__ float  sGr[32][33];
    __shared__ float  sGi[32][33];
    int k  = blockIdx.z;
    int q0 = blockIdx.x * 32;
    int m0 = blockIdx.y * 64;
    int tx = threadIdx.x, ty = threadIdx.y;
    int tid = ty*32 + tx;
    for (int j = tid; j < D1; j += 256) stw[j] = g_tw[j];

    int q = q0 + tx;
    bool qv = (q < D2R);

    float accr[8], acci[8];
    int   jm[8], ms[8];
#pragma unroll
    for (int mm = 0; mm < 8; ++mm) {
        accr[mm] = 0.f; acci[mm] = 0.f;
        ms[mm] = m0 + ty*8 + mm;
        jm[mm] = 0;
    }

    for (int p0 = 0; p0 < D1; p0 += 32) {
        __syncthreads();
#pragma unroll
        for (int r = 0; r < 4; ++r) {
            int pl = ty*4 + r;
            int p  = p0 + pl;
            sGr[pl][tx] = qv ? g_Gr[k][p*D2R + q] : 0.f;
            sGi[pl][tx] = qv ? g_Gi[k][p*D2R + q] : 0.f;
        }
        __syncthreads();
#pragma unroll
        for (int pl = 0; pl < 32; ++pl) {
            float gr = sGr[pl][tx];
            float gi = sGi[pl][tx];
#pragma unroll
            for (int mm = 0; mm < 8; ++mm) {
                float2 cs = stw[jm[mm]];
                accr[mm] += cs.x*gr - cs.y*gi;
                acci[mm] += cs.x*gi + cs.y*gr;
                jm[mm] += ms[mm];
                if (jm[mm] >= D1) jm[mm] -= D1;
            }
        }
    }

    if (qv) {
        bool edge = (q == 0) || (q == 384);
        float sc  = (edge ? 1.f : 2.f) * (1.f/((float)D1*(float)D2));
        float sci = edge ? 0.f : sc;
#pragma unroll
        for (int mm = 0; mm < 8; ++mm) {
            g_Yr[k][ms[mm]*D2R + q] = accr[mm]*sc;
            g_Yi[k][ms[mm]*D2R + q] = acci[mm]*sci;
        }
    }
}

// ---------------- axis-1 irfft (385 -> 768 real) ---------------------------
__global__ void __launch_bounds__(256) k_irfftQ() {
    __shared__ float2 stw[D1];
    __shared__ __align__(16) float sYr[32][68];
    __shared__ __align__(16) float sYi[32][68];
    int k  = blockIdx.z;
    int t0 = blockIdx.x * 32;
    int m0 = blockIdx.y * 64;
    int tx = threadIdx.x, ty = threadIdx.y;
    int tid = ty*32 + tx;
    for (int j = tid; j < D1; j += 256) stw[j] = g_tw[j];

    int t = t0 + tx;
    float acc[8];
#pragma unroll
    for (int mm = 0; mm < 8; ++mm) acc[mm] = 0.f;
    int jq = 0;

    for (int q0 = 0; q0 < D2R; q0 += 32) {
        __syncthreads();
#pragma unroll
        for (int r = 0; r < 8; ++r) {
            int ml = ty*8 + r;
            int q  = q0 + tx;
            bool v = (q < D2R);
            sYr[tx][ml] = v ? g_Yr[k][(m0+ml)*D2R + q] : 0.f;
            sYi[tx][ml] = v ? g_Yi[k][(m0+ml)*D2R + q] : 0.f;
        }
        __syncthreads();
#pragma unroll
        for (int ql = 0; ql < 32; ++ql) {
            float2 cs = stw[jq];
            const float4* pr = (const float4*)&sYr[ql][ty*8];
            const float4* pi = (const float4*)&sYi[ql][ty*8];
            float4 r0 = pr[0], r1 = pr[1];
            float4 i0 = pi[0], i1 = pi[1];
            acc[0] += cs.x*r0.x - cs.y*i0.x;
            acc[1] += cs.x*r0.y - cs.y*i0.y;
            acc[2] += cs.x*r0.z - cs.y*i0.z;
            acc[3] += cs.x*r0.w - cs.y*i0.w;
            acc[4] += cs.x*r1.x - cs.y*i1.x;
            acc[5] += cs.x*r1.y - cs.y*i1.y;
            acc[6] += cs.x*r1.z - cs.y*i1.z;
            acc[7] += cs.x*r1.w - cs.y*i1.w;
            jq += t;
            if (jq >= D1) jq -= D1;
        }
    }
#pragma unroll
    for (int mm = 0; mm < 8; ++mm)
        g_S[k][(m0 + ty*8 + mm)*D2 + t] = acc[mm];
}

// ------------- combine per-batch weights -> bf16 hi/lo, K-major ------------
// flat id = ((b*256+o)*9+st)*256 + i
__global__ void k_combine_bf16() {
    int id = blockIdx.x * 256 + threadIdx.x;
    int i  = id & 255;
    int r  = id >> 8;          // (b*256+o)*9 + st
    int st = r % 9;
    int bo = r / 9;
    int o  = bo & 255;
    int b  = bo >> 8;
    int s = st / 3, tt = st % 3;
    int sidx = (o*3 + s)*D2 + i*3 + tt;
    float v = 0.f;
#pragma unroll
    for (int k = 0; k < KN_; ++k)
        v += g_att[b*KN_ + k] * g_S[k][sidx];
    __nv_bfloat16 hi = __float2bfloat16(v);
    g_Whi[id] = hi;
    g_Wlo[id] = __float2bfloat16(v - __bfloat162float(hi));
}

// ------------- x: split to bf16 hi/lo + transpose to channel-last ----------
__global__ void k_xsplit(const float* __restrict__ xin) {
    __shared__ float tile[32][33];
    int b  = blockIdx.z;
    int p0 = blockIdx.x * 32;    // pixel
    int c0 = blockIdx.y * 32;    // channel
    int tx = threadIdx.x, ty = threadIdx.y;   // 32 x 8
#pragma unroll
    for (int j = 0; j < 4; ++j) {
        int ch = c0 + ty + j*8;
        tile[ty + j*8][tx] = xin[((size_t)b*C_ + ch)*(HW_*HW_) + p0 + tx];
    }
    __syncthreads();
#pragma unroll
    for (int j = 0; j < 4; ++j) {
        int p = p0 + ty + j*8;
        float v = tile[tx][ty + j*8];
        __nv_bfloat16 hi = __float2bfloat16(v);
        size_t oidx = ((size_t)b*(HW_*HW_) + p)*C_ + c0 + tx;
        g_Xhi[oidx] = hi;
        g_Xlo[oidx] = __float2bfloat16(v - __bfloat162float(hi));
    }
}

// ---------------- wmma bf16 implicit-GEMM conv -----------------------------
// CTA: M=128 out-ch x N=128 pixels (2 rows of 64). 8 warps, each 64x32.
// K: 3 passes x 9 taps x 8 chunks of 32 channels = 216 chunks.
#define KC 32
#define AST 40               // smem row stride in elements (pad vs bank conflicts)
#define NCHUNK 216

__global__ void __launch_bounds__(256) k_conv_wmma(float* __restrict__ out) {
    __shared__ __nv_bfloat16 sA[2][128*AST];
    __shared__ __nv_bfloat16 sB[2][128*AST];

    int tid = threadIdx.x;
    int wid = tid >> 5;
    int warp_m = wid >> 2;            // 0..1  -> M offset *64
    int warp_n = wid & 3;             // 0..3  -> N offset *32
    int b  = blockIdx.z;
    int o0 = blockIdx.y * 128;
    int n0 = blockIdx.x * 128;        // pixel base

    // per-thread load mapping: row = tid/2 (0..127), 16 elems at (tid&1)*16
    int lrow  = tid >> 1;
    int lhalf = (tid & 1) << 4;

    uint32_t aBase[2] = { smem_u32(&sA[0][0]), smem_u32(&sA[1][0]) };
    uint32_t bBase[2] = { smem_u32(&sB[0][0]), smem_u32(&sB[1][0]) };
    uint32_t aDst0 = (uint32_t)(lrow*AST + lhalf) * 2;   // byte offset within buffer
    uint32_t bDst0 = aDst0;

    wmma::fragment<wmma::accumulator, 16, 16, 16, float> acc[4][2];
#pragma unroll
    for (int i = 0; i < 4; ++i)
#pragma unroll
        for (int j = 0; j < 2; ++j)
            wmma::fill_fragment(acc[i][j], 0.f);

    // ---- chunk issue: global -> smem via cp.async ----
    auto issue = [&](int c, int buf) {
        int pass = c / 72;
        int rem  = c % 72;
        int st   = rem >> 3;
        int i0   = (rem & 7) << 5;
        int s    = st / 3, t = st % 3;
        const __nv_bfloat16* Wp = (pass == 2) ? g_Wlo : g_Whi;
        const __nv_bfloat16* Xp = (pass == 1) ? g_Xlo : g_Xhi;

        // A: weights, row o0+lrow, K slice [st*256 + i0 + lhalf, +16)
        const __nv_bfloat16* asrc = Wp + (size_t)b*(C_*9*C_)
                                    + (size_t)(o0 + lrow)*2304 + st*256 + i0 + lhalf;
        uint32_t ad = aBase[buf] + aDst0;
        cp_async16(ad,      asrc,     16);
        cp_async16(ad + 16, asrc + 8, 16);

        // B: im2col pixel row n0+lrow, tap (s,t), channels [i0+lhalf, +16)
        int n  = n0 + lrow;
        int yy = (n >> 6) + s - 1;
        int xx = (n & 63) + t - 1;
        int ok = (((unsigned)yy < HW_) && ((unsigned)xx < HW_)) ? 16 : 0;
        const __nv_bfloat16* bsrc = Xp + (((size_t)b*(HW_*HW_) + yy*HW_ + xx)*C_
                                          + i0 + lhalf);
        uint32_t bd = bBase[buf] + bDst0;
        cp_async16(bd,      bsrc,     ok);
        cp_async16(bd + 16, bsrc + 8, ok);
        CP_COMMIT();
    };

    issue(0, 0);

    for (int c = 0; c < NCHUNK; ++c) {
        int buf = c & 1;
        if (c + 1 < NCHUNK) {
            issue(c + 1, (c + 1) & 1);
            CP_WAIT(1);
        } else {
            CP_WAIT(0);
        }
        __syncthreads();

#pragma unroll
        for (int kk = 0; kk < 2; ++kk) {
            wmma::fragment<wmma::matrix_a, 16, 16, 16, __nv_bfloat16, wmma::row_major> af[4];
            wmma::fragment<wmma::matrix_b, 16, 16, 16, __nv_bfloat16, wmma::col_major> bfr[2];
#pragma unroll
            for (int i = 0; i < 4; ++i)
                wmma::load_matrix_sync(af[i],
                    &sA[buf][(warp_m*64 + i*16)*AST + kk*16], AST);
#pragma unroll
            for (int j = 0; j < 2; ++j)
                wmma::load_matrix_sync(bfr[j],
                    &sB[buf][(warp_n*32 + j*16)*AST + kk*16], AST);
#pragma unroll
            for (int i = 0; i < 4; ++i)
#pragma unroll
                for (int j = 0; j < 2; ++j)
                    wmma::mma_sync(acc[i][j], af[i], bfr[j], acc[i][j]);
        }
        __syncthreads();
    }

    // ---- epilogue: direct fp32 store, pixels contiguous per out-ch row ----
    float* ob = out + ((size_t)b*C_ + o0 + warp_m*64)*(HW_*HW_) + n0 + warp_n*32;
#pragma unroll
    for (int i = 0; i < 4; ++i)
#pragma unroll
        for (int j = 0; j < 2; ++j)
            wmma::store_matrix_sync(ob + (size_t)i*16*(HW_*HW_) + j*16,
                                    acc[i][j], HW_*HW_, wmma::mem_row_major);
}

// ---------------- launch ----------------------------------------------------
extern "C" void kernel_launch(void* const* d_in, const int* in_sizes, int n_in,
                              void* d_out, int out_size) {
    const float* x    = (const float*)d_in[0];
    const float* dw   = (const float*)d_in[1];
    const float* katt = (const float*)d_in[2];
    const int*   fh   = (const int*)d_in[3];
    const int*   fw   = (const int*)d_in[4];
    float* out = (float*)d_out;

    k_setup       <<<1, 768>>>(katt);
    k_scatter     <<<(NF + 255)/256, 256>>>(dw, fh, fw);
    k_xsplit      <<<dim3(HW_*HW_/32, C_/32, B_), dim3(32, 8)>>>(x);
    k_dftP        <<<dim3(13, 12, KN_), dim3(32, 8)>>>();
    k_irfftQ      <<<dim3(24, 12, KN_), dim3(32, 8)>>>();
    k_combine_bf16<<<(B_*C_*C_*9)/256, 256>>>();
    k_conv_wmma   <<<dim3(HW_*HW_/128, C_/128, B_), 256>>>(out);
}

// round 6
// speedup vs baseline: 1.7884x; 1.3090x over previous
#include <cuda_runtime.h>
#include <cuda_bf16.h>
#include <mma.h>
#include <math.h>
#include <stdint.h>

using namespace nvcuda;

#define D1 768
#define D2 768
#define D2R 385
#define NF (D1*D2R)     // 295680
#define KN_ 4
#define B_ 8
#define C_ 256
#define HW_ 64

// GEMM layout constants
#define QPAD 512          // padded N for stage A (q dimension)
#define KB2  800          // padded K for stage B (770 -> 800)

// ---------------- scratch (static device globals; no allocation) ----------
__device__ float  g_att[B_*KN_];
__device__ float2 g_tw[D1];                 // (cos, sin) of 2*pi*j/768

// Stage A operands: A = stacked twiddles [1536][1536]; B = G^T [k][512][1536]
__device__ __align__(128) __nv_bfloat16 g_TA_hi[1536*1536];
__device__ __align__(128) __nv_bfloat16 g_TA_lo[1536*1536];
__device__ __align__(128) __nv_bfloat16 g_GT_hi[KN_*QPAD*1536];
__device__ __align__(128) __nv_bfloat16 g_GT_lo[KN_*QPAD*1536];
// Stage A output (fp32): [k][1536][512]  (rows 0..767 = Yr, 768..1535 = Yi)
__device__ __align__(128) float g_Ytmp[KN_*1536*QPAD];
// Stage B operands: A = scaled Y [3072][800]; B = irfft twiddles [768][800]
__device__ __align__(128) __nv_bfloat16 g_YA_hi[KN_*D1*KB2];
__device__ __align__(128) __nv_bfloat16 g_YA_lo[KN_*D1*KB2];
__device__ __align__(128) __nv_bfloat16 g_TB_hi[D2*KB2];
__device__ __align__(128) __nv_bfloat16 g_TB_lo[D2*KB2];
// spatial weights [k][m][t]
__device__ __align__(128) float g_S[KN_][D1*D2];

// bf16 hi/lo weights, per batch, K-major rows: [b][o][st*256 + i]
__device__ __align__(128) __nv_bfloat16 g_Whi[B_*C_*9*C_];
__device__ __align__(128) __nv_bfloat16 g_Wlo[B_*C_*9*C_];
// bf16 hi/lo input, channel-last: [b][pixel][i]
__device__ __align__(128) __nv_bfloat16 g_Xhi[B_*HW_*HW_*C_];
__device__ __align__(128) __nv_bfloat16 g_Xlo[B_*HW_*HW_*C_];

// ============================ helpers ======================================
__device__ __forceinline__ uint32_t smem_u32(const void* p) {
    uint32_t a;
    asm("{ .reg .u64 t; cvta.to.shared.u64 t, %1; cvt.u32.u64 %0, t; }"
        : "=r"(a) : "l"(p));
    return a;
}
__device__ __forceinline__ void cp_async16(uint32_t dst, const void* src, int pbytes) {
    asm volatile("cp.async.cg.shared.global [%0], [%1], 16, %2;"
                 :: "r"(dst), "l"(src), "r"(pbytes));
}
#define CP_COMMIT() asm volatile("cp.async.commit_group;" ::: "memory")
#define CP_WAIT(N)  asm volatile("cp.async.wait_group %0;" :: "n"(N) : "memory")

__device__ __forceinline__ void bf16_split(float v, __nv_bfloat16& hi, __nv_bfloat16& lo) {
    hi = __float2bfloat16(v);
    lo = __float2bfloat16(v - __bfloat162float(hi));
}

// ---------------- setup: attention + twiddle table -------------------------
__global__ void k_setup(const float* __restrict__ katt) {
    int j = threadIdx.x;
    if (j < D1) {
        double ang = 2.0 * M_PI * (double)j / (double)D1;
        g_tw[j] = make_float2((float)cos(ang), (float)sin(ang));
    }
    if (j < B_*KN_) {
        g_att[j] = 0.5f / (1.0f + expf(-katt[j]));
    }
}

// ---------------- fill stage-A twiddle matrix (1536x1536) ------------------
// A2[i][j]: i<768 row m of Yr: [C | -S];  i>=768 row m of Yi: [S | C]
__global__ void k_fillTA() {
    int id = blockIdx.x * 256 + threadIdx.x;
    if (id >= 1536*1536) return;
    int i = id / 1536;
    int j = id - i*1536;
    int m = (i < 768) ? i : i - 768;
    int p = (j < 768) ? j : j - 768;
    int idx = (m * p) % 768;
    float2 cs = g_tw[idx];
    float v = (i < 768) ? ((j < 768) ? cs.x : -cs.y)
                        : ((j < 768) ? cs.y :  cs.x);
    __nv_bfloat16 hi, lo; bf16_split(v, hi, lo);
    g_TA_hi[id] = hi; g_TA_lo[id] = lo;
}

// ---------------- fill stage-B twiddle matrix (768 x 800) ------------------
// row t: cols 0..384 = cos(2*pi*q*t/768); 385..769 = -sin; 770..799 = 0
__global__ void k_fillTB() {
    int id = blockIdx.x * 256 + threadIdx.x;
    if (id >= D2*KB2) return;
    int t = id / KB2;
    int c = id - t*KB2;
    float v = 0.f;
    if (c < 385) {
        v = g_tw[(c * t) % 768].x;
    } else if (c < 770) {
        int q = c - 385;
        v = -g_tw[(q * t) % 768].y;
    }
    __nv_bfloat16 hi, lo; bf16_split(v, hi, lo);
    g_TB_hi[id] = hi; g_TB_lo[id] = lo;
}

// ---------------- scatter dft_weight into transposed G, bf16 hi/lo ---------
// G^T[k][q][p2]: p2<768 -> Gr[p][q]; p2>=768 -> Gi[p][q]
__global__ void k_scatter(const float* __restrict__ dw,
                          const int*   __restrict__ fh,
                          const int*   __restrict__ fw) {
    int n = blockIdx.x * 256 + threadIdx.x;
    if (n >= NF) return;
    int p = fh[n];
    int q = fw[n];
    const float2* dw2 = (const float2*)dw;
#pragma unroll
    for (int k = 0; k < KN_; ++k) {
        float2 v = dw2[(size_t)k*NF + n];
        size_t base = (size_t)k*(QPAD*1536) + (size_t)q*1536;
        __nv_bfloat16 hi, lo;
        bf16_split(v.x, hi, lo);
        g_GT_hi[base + p] = hi;       g_GT_lo[base + p] = lo;
        bf16_split(v.y, hi, lo);
        g_GT_hi[base + 768 + p] = hi; g_GT_lo[base + 768 + p] = lo;
    }
}

// ---------------- convert stage-A output -> stage-B A operand --------------
// Y scaled by (edge?1:2)/768^2, Yi zeroed at edges; layout [k*768+m][800]
__global__ void k_yconv() {
    int id = blockIdx.x * 256 + threadIdx.x;
    if (id >= KN_*D1*D2R) return;
    int q = id % D2R;
    int r = id / D2R;          // k*768 + m
    int m = r % D1;
    int k = r / D1;
    const float* Yk = g_Ytmp + (size_t)k*(1536*QPAD);
    float yr = Yk[(size_t)m*QPAD + q];
    float yi = Yk[(size_t)(768 + m)*QPAD + q];
    bool edge = (q == 0) || (q == 384);
    float sc  = (edge ? 1.f : 2.f) * (1.f/((float)D1*(float)D2));
    yr *= sc;
    yi  = edge ? 0.f : yi*sc;
    size_t base = (size_t)r*KB2;
    __nv_bfloat16 hi, lo;
    bf16_split(yr, hi, lo);
    g_YA_hi[base + q] = hi;        g_YA_lo[base + q] = lo;
    bf16_split(yi, hi, lo);
    g_YA_hi[base + 385 + q] = hi;  g_YA_lo[base + 385 + q] = lo;
}

// ---------------- generic bf16 hi/lo 3-pass wmma GEMM body -----------------
// CTA: 128(M) x 128(N) tile, 8 warps of 64x32. A row-major [M][lda],
// B stored as [N][ldb] (K contiguous per row). K padded to mult of 32.
// Pointers must be computed in DEVICE code (device globals are not valid
// host-side kernel arguments).
#define AST 40

__device__ __forceinline__ void gemm_body(
    const __nv_bfloat16* Ah, const __nv_bfloat16* Al, int lda,
    const __nv_bfloat16* Bh, const __nv_bfloat16* Bl, int ldb,
    float* Cc, int ldc, int K32)
{
    __shared__ __nv_bfloat16 sA[2][128*AST];
    __shared__ __nv_bfloat16 sB[2][128*AST];

    int tid = threadIdx.x;
    int wid = tid >> 5;
    int warp_m = wid >> 2;
    int warp_n = wid & 3;
    int m0 = blockIdx.y * 128;
    int n0 = blockIdx.x * 128;

    int lrow  = tid >> 1;
    int lhalf = (tid & 1) << 4;

    uint32_t aBase[2] = { smem_u32(&sA[0][0]), smem_u32(&sA[1][0]) };
    uint32_t bBase[2] = { smem_u32(&sB[0][0]), smem_u32(&sB[1][0]) };
    uint32_t dOff = (uint32_t)(lrow*AST + lhalf) * 2;

    wmma::fragment<wmma::accumulator, 16, 16, 16, float> acc[4][2];
#pragma unroll
    for (int i = 0; i < 4; ++i)
#pragma unroll
        for (int j = 0; j < 2; ++j)
            wmma::fill_fragment(acc[i][j], 0.f);

    int nchunk = 3*K32;

    auto issue = [&](int c, int buf) {
        int pass = (c >= 2*K32) ? 2 : ((c >= K32) ? 1 : 0);
        int k0   = (c - pass*K32) * 32;
        const __nv_bfloat16* Ap = (pass == 2) ? Al : Ah;
        const __nv_bfloat16* Bp = (pass == 1) ? Bl : Bh;

        const __nv_bfloat16* asrc = Ap + (size_t)(m0 + lrow)*lda + k0 + lhalf;
        uint32_t ad = aBase[buf] + dOff;
        cp_async16(ad,      asrc,     16);
        cp_async16(ad + 16, asrc + 8, 16);

        const __nv_bfloat16* bsrc = Bp + (size_t)(n0 + lrow)*ldb + k0 + lhalf;
        uint32_t bd = bBase[buf] + dOff;
        cp_async16(bd,      bsrc,     16);
        cp_async16(bd + 16, bsrc + 8, 16);
        CP_COMMIT();
    };

    issue(0, 0);

    for (int c = 0; c < nchunk; ++c) {
        int buf = c & 1;
        if (c + 1 < nchunk) {
            issue(c + 1, (c + 1) & 1);
            CP_WAIT(1);
        } else {
            CP_WAIT(0);
        }
        __syncthreads();

#pragma unroll
        for (int kk = 0; kk < 2; ++kk) {
            wmma::fragment<wmma::matrix_a, 16, 16, 16, __nv_bfloat16, wmma::row_major> af[4];
            wmma::fragment<wmma::matrix_b, 16, 16, 16, __nv_bfloat16, wmma::col_major> bfr[2];
#pragma unroll
            for (int i = 0; i < 4; ++i)
                wmma::load_matrix_sync(af[i],
                    &sA[buf][(warp_m*64 + i*16)*AST + kk*16], AST);
#pragma unroll
            for (int j = 0; j < 2; ++j)
                wmma::load_matrix_sync(bfr[j],
                    &sB[buf][(warp_n*32 + j*16)*AST + kk*16], AST);
#pragma unroll
            for (int i = 0; i < 4; ++i)
#pragma unroll
                for (int j = 0; j < 2; ++j)
                    wmma::mma_sync(acc[i][j], af[i], bfr[j], acc[i][j]);
        }
        __syncthreads();
    }

    float* ob = Cc + (size_t)(m0 + warp_m*64)*ldc + n0 + warp_n*32;
#pragma unroll
    for (int i = 0; i < 4; ++i)
#pragma unroll
        for (int j = 0; j < 2; ++j)
            wmma::store_matrix_sync(ob + (size_t)i*16*ldc + j*16,
                                    acc[i][j], ldc, wmma::mem_row_major);
}

// Stage A: [Yr;Yi](1536 x 512) = TA(1536x1536) * G^T, per k (blockIdx.z)
__global__ void __launch_bounds__(256) k_gemmA() {
    int z = blockIdx.z;
    gemm_body(g_TA_hi, g_TA_lo, 1536,
              g_GT_hi + (size_t)z*(QPAD*1536), g_GT_lo + (size_t)z*(QPAD*1536), 1536,
              g_Ytmp + (size_t)z*(1536*QPAD), QPAD,
              1536/32);
}

// Stage B: S(3072 x 768) = YA(3072x800) * TB^T
__global__ void __launch_bounds__(256) k_gemmB() {
    gemm_body(g_YA_hi, g_YA_lo, KB2,
              g_TB_hi, g_TB_lo, KB2,
              &g_S[0][0], D2,
              KB2/32);
}

// ------------- combine per-batch weights -> bf16 hi/lo, K-major ------------
__global__ void k_combine_bf16() {
    int id = blockIdx.x * 256 + threadIdx.x;
    int i  = id & 255;
    int r  = id >> 8;          // (b*256+o)*9 + st
    int st = r % 9;
    int bo = r / 9;
    int o  = bo & 255;
    int b  = bo >> 8;
    int s = st / 3, tt = st % 3;
    int sidx = (o*3 + s)*D2 + i*3 + tt;
    float v = 0.f;
#pragma unroll
    for (int k = 0; k < KN_; ++k)
        v += g_att[b*KN_ + k] * g_S[k][sidx];
    __nv_bfloat16 hi, lo; bf16_split(v, hi, lo);
    g_Whi[id] = hi;
    g_Wlo[id] = lo;
}

// ------------- x: split to bf16 hi/lo + transpose to channel-last ----------
__global__ void k_xsplit(const float* __restrict__ xin) {
    __shared__ float tile[32][33];
    int b  = blockIdx.z;
    int p0 = blockIdx.x * 32;
    int c0 = blockIdx.y * 32;
    int tx = threadIdx.x, ty = threadIdx.y;   // 32 x 8
#pragma unroll
    for (int j = 0; j < 4; ++j) {
        int ch = c0 + ty + j*8;
        tile[ty + j*8][tx] = xin[((size_t)b*C_ + ch)*(HW_*HW_) + p0 + tx];
    }
    __syncthreads();
#pragma unroll
    for (int j = 0; j < 4; ++j) {
        int p = p0 + ty + j*8;
        float v = tile[tx][ty + j*8];
        __nv_bfloat16 hi, lo; bf16_split(v, hi, lo);
        size_t oidx = ((size_t)b*(HW_*HW_) + p)*C_ + c0 + tx;
        g_Xhi[oidx] = hi;
        g_Xlo[oidx] = lo;
    }
}

// ---------------- wmma bf16 implicit-GEMM conv -----------------------------
#define NCHUNK 216

__global__ void __launch_bounds__(256) k_conv_wmma(float* __restrict__ out) {
    __shared__ __nv_bfloat16 sA[2][128*AST];
    __shared__ __nv_bfloat16 sB[2][128*AST];

    int tid = threadIdx.x;
    int wid = tid >> 5;
    int warp_m = wid >> 2;
    int warp_n = wid & 3;
    int b  = blockIdx.z;
    int o0 = blockIdx.y * 128;
    int n0 = blockIdx.x * 128;

    int lrow  = tid >> 1;
    int lhalf = (tid & 1) << 4;

    uint32_t aBase[2] = { smem_u32(&sA[0][0]), smem_u32(&sA[1][0]) };
    uint32_t bBase[2] = { smem_u32(&sB[0][0]), smem_u32(&sB[1][0]) };
    uint32_t aDst0 = (uint32_t)(lrow*AST + lhalf) * 2;
    uint32_t bDst0 = aDst0;

    wmma::fragment<wmma::accumulator, 16, 16, 16, float> acc[4][2];
#pragma unroll
    for (int i = 0; i < 4; ++i)
#pragma unroll
        for (int j = 0; j < 2; ++j)
            wmma::fill_fragment(acc[i][j], 0.f);

    auto issue = [&](int c, int buf) {
        int pass = c / 72;
        int rem  = c % 72;
        int st   = rem >> 3;
        int i0   = (rem & 7) << 5;
        int s    = st / 3, t = st % 3;
        const __nv_bfloat16* Wp = (pass == 2) ? g_Wlo : g_Whi;
        const __nv_bfloat16* Xp = (pass == 1) ? g_Xlo : g_Xhi;

        const __nv_bfloat16* asrc = Wp + (size_t)b*(C_*9*C_)
                                    + (size_t)(o0 + lrow)*2304 + st*256 + i0 + lhalf;
        uint32_t ad = aBase[buf] + aDst0;
        cp_async16(ad,      asrc,     16);
        cp_async16(ad + 16, asrc + 8, 16);

        int n  = n0 + lrow;
        int yy = (n >> 6) + s - 1;
        int xx = (n & 63) + t - 1;
        int ok = (((unsigned)yy < HW_) && ((unsigned)xx < HW_)) ? 16 : 0;
        const __nv_bfloat16* bsrc = Xp + (((size_t)b*(HW_*HW_) + yy*HW_ + xx)*C_
                                          + i0 + lhalf);
        uint32_t bd = bBase[buf] + bDst0;
        cp_async16(bd,      bsrc,     ok);
        cp_async16(bd + 16, bsrc + 8, ok);
        CP_COMMIT();
    };

    issue(0, 0);

    for (int c = 0; c < NCHUNK; ++c) {
        int buf = c & 1;
        if (c + 1 < NCHUNK) {
            issue(c + 1, (c + 1) & 1);
            CP_WAIT(1);
        } else {
            CP_WAIT(0);
        }
        __syncthreads();

#pragma unroll
        for (int kk = 0; kk < 2; ++kk) {
            wmma::fragment<wmma::matrix_a, 16, 16, 16, __nv_bfloat16, wmma::row_major> af[4];
            wmma::fragment<wmma::matrix_b, 16, 16, 16, __nv_bfloat16, wmma::col_major> bfr[2];
#pragma unroll
            for (int i = 0; i < 4; ++i)
                wmma::load_matrix_sync(af[i],
                    &sA[buf][(warp_m*64 + i*16)*AST + kk*16], AST);
#pragma unroll
            for (int j = 0; j < 2; ++j)
                wmma::load_matrix_sync(bfr[j],
                    &sB[buf][(warp_n*32 + j*16)*AST + kk*16], AST);
#pragma unroll
            for (int i = 0; i < 4; ++i)
#pragma unroll
                for (int j = 0; j < 2; ++j)
                    wmma::mma_sync(acc[i][j], af[i], bfr[j], acc[i][j]);
        }
        __syncthreads();
    }

    float* ob = out + ((size_t)b*C_ + o0 + warp_m*64)*(HW_*HW_) + n0 + warp_n*32;
#pragma unroll
    for (int i = 0; i < 4; ++i)
#pragma unroll
        for (int j = 0; j < 2; ++j)
            wmma::store_matrix_sync(ob + (size_t)i*16*(HW_*HW_) + j*16,
                                    acc[i][j], HW_*HW_, wmma::mem_row_major);
}

// ---------------- launch ----------------------------------------------------
extern "C" void kernel_launch(void* const* d_in, const int* in_sizes, int n_in,
                              void* d_out, int out_size) {
    const float* x    = (const float*)d_in[0];
    const float* dw   = (const float*)d_in[1];
    const float* katt = (const float*)d_in[2];
    const int*   fh   = (const int*)d_in[3];
    const int*   fw   = (const int*)d_in[4];
    float* out = (float*)d_out;

    k_setup  <<<1, 768>>>(katt);
    k_fillTA <<<(1536*1536 + 255)/256, 256>>>();
    k_fillTB <<<(D2*KB2 + 255)/256, 256>>>();
    k_scatter<<<(NF + 255)/256, 256>>>(dw, fh, fw);
    k_xsplit <<<dim3(HW_*HW_/32, C_/32, B_), dim3(32, 8)>>>(x);

    k_gemmA<<<dim3(QPAD/128, 1536/128, KN_), 256>>>();
    k_yconv<<<(KN_*D1*D2R + 255)/256, 256>>>();
    k_gemmB<<<dim3(D2/128, (KN_*D1)/128, 1), 256>>>();

    k_combine_bf16<<<(B_*C_*C_*9)/256, 256>>>();
    k_conv_wmma   <<<dim3(HW_*HW_/128, C_/128, B_), 256>>>(out);
}